// round 1
// baseline (speedup 1.0000x reference)
#include <cuda_runtime.h>

// ---------------- problem constants ----------------
#define BATCH   256
#define NH      12
#define HD      64
#define DIM     768          // NH*HD
#define WIN     14
#define NTOK    196          // WIN*WIN
#define MTOT    (BATCH*NTOK) // 50176
#define REL     27           // 2*WIN-1

// ---------------- scratch (device globals; no allocation allowed) -------
__device__ float g_q[BATCH*NH*NTOK*HD];   // [b][h][n][d], pre-scaled by 1/8
__device__ float g_k[BATCH*NH*NTOK*HD];
__device__ float g_v[BATCH*NH*NTOK*HD];
__device__ float g_ao[MTOT*DIM];          // attention output [b][n][h*64+d]

// =========================================================================
// GEMM: C[m][c] = sum_k A[m][k] * B[c][k]  (+bias)   -- both K-major, K=768
// 128x128 tile, BK=8, 256 threads, 8x8 register microtile.
// MODE 0: QKV epilogue (scatter into g_q/g_k/g_v, scale q)
// MODE 1: plain epilogue into `out` (proj)
// =========================================================================
template<int MODE>
__global__ __launch_bounds__(256) void gemm_nt(const float* __restrict__ A,
                                               const float* __restrict__ Bm,
                                               const float* __restrict__ bias,
                                               float* __restrict__ out)
{
    __shared__ float As[8 * 128];
    __shared__ float Bs[8 * 128];

    const int tid = threadIdx.x;
    const int m0  = blockIdx.y * 128;
    const int n0  = blockIdx.x * 128;

    const int lr = tid >> 1;          // 0..127 : tile row loaded by this thread
    const int lc = (tid & 1) * 4;     // 0 or 4 : k-offset
    const int trow = (tid >> 4) * 8;  // 0..120
    const int tcol = (tid & 15) * 8;  // 0..120

    float acc[8][8];
#pragma unroll
    for (int i = 0; i < 8; i++)
#pragma unroll
        for (int j = 0; j < 8; j++) acc[i][j] = 0.f;

    const float* Ap = (MODE == 1 ? g_ao : A) + (m0 + lr) * 768 + lc;
    const float* Bp = Bm + (n0 + lr) * 768 + lc;

    for (int k0 = 0; k0 < 768; k0 += 8) {
        float4 av = *(const float4*)(Ap + k0);
        float4 bv = *(const float4*)(Bp + k0);
        As[(lc + 0) * 128 + lr] = av.x;
        As[(lc + 1) * 128 + lr] = av.y;
        As[(lc + 2) * 128 + lr] = av.z;
        As[(lc + 3) * 128 + lr] = av.w;
        Bs[(lc + 0) * 128 + lr] = bv.x;
        Bs[(lc + 1) * 128 + lr] = bv.y;
        Bs[(lc + 2) * 128 + lr] = bv.z;
        Bs[(lc + 3) * 128 + lr] = bv.w;
        __syncthreads();
#pragma unroll
        for (int kk = 0; kk < 8; kk++) {
            float a[8], b[8];
            *(float4*)(a)     = *(const float4*)&As[kk * 128 + trow];
            *(float4*)(a + 4) = *(const float4*)&As[kk * 128 + trow + 4];
            *(float4*)(b)     = *(const float4*)&Bs[kk * 128 + tcol];
            *(float4*)(b + 4) = *(const float4*)&Bs[kk * 128 + tcol + 4];
#pragma unroll
            for (int i = 0; i < 8; i++)
#pragma unroll
                for (int j = 0; j < 8; j++) acc[i][j] += a[i] * b[j];
        }
        __syncthreads();
    }

    // ----- epilogue -----
#pragma unroll
    for (int i = 0; i < 8; i++) {
        const int m = m0 + trow + i;
        if (MODE == 0) {
            const int b = m / NTOK;
            const int n = m - b * NTOK;
#pragma unroll
            for (int j = 0; j < 8; j++) {
                const int col = n0 + tcol + j;
                float v = acc[i][j] + bias[col];
                const int which = col / DIM;          // 0=q,1=k,2=v
                const int rem   = col - which * DIM;
                const int h     = rem >> 6;
                const int dd    = rem & 63;
                const int idx   = ((b * NH + h) * NTOK + n) * HD + dd;
                if (which == 0)      g_q[idx] = v * 0.125f;  // 64^-0.5
                else if (which == 1) g_k[idx] = v;
                else                 g_v[idx] = v;
            }
        } else {
#pragma unroll
            for (int j = 0; j < 8; j++) {
                const int col = n0 + tcol + j;
                out[m * DIM + col] = acc[i][j] + bias[col];
            }
        }
    }
}

// =========================================================================
// Fused attention: one CTA per (b,h). K/V + rel tables in SMEM.
// Thread i (<196) owns query i: online softmax (lazy rescale), 64-wide
// accumulator in registers. Bias decomposed: bias(q,kh,kw)=bh[kh]+bw[kw].
// =========================================================================
#define SM_KS 0
#define SM_VS (NTOK*HD)                 // 12544
#define SM_RH (2*NTOK*HD)               // 25088
#define SM_RW (SM_RH + REL*HD)          // +1728
#define SM_BH (SM_RW + REL*HD)
#define SM_BW (SM_BH + NTOK*WIN)        // 196*14 = 2744
#define SM_TOT (SM_BW + NTOK*WIN)       // 34032 floats = 136128 B

__global__ __launch_bounds__(224, 1) void attn_kernel(const float* __restrict__ relh,
                                                      const float* __restrict__ relw)
{
    extern __shared__ float sm[];
    float* Ks = sm + SM_KS;
    float* Vs = sm + SM_VS;
    float* Rh = sm + SM_RH;
    float* Rw = sm + SM_RW;
    float* BH = sm + SM_BH;
    float* BW = sm + SM_BW;

    const int bh  = blockIdx.x;          // b*12 + h
    const int tid = threadIdx.x;

    const float4* kbase = (const float4*)(g_k + bh * NTOK * HD);
    const float4* vbase = (const float4*)(g_v + bh * NTOK * HD);
    for (int idx = tid; idx < NTOK * HD / 4; idx += 224) {
        ((float4*)Ks)[idx] = kbase[idx];
        ((float4*)Vs)[idx] = vbase[idx];
    }
    for (int idx = tid; idx < REL * HD / 4; idx += 224) {
        ((float4*)Rh)[idx] = ((const float4*)relh)[idx];
        ((float4*)Rw)[idx] = ((const float4*)relw)[idx];
    }
    __syncthreads();

    const int i = tid;
    if (i < NTOK) {
        float4 q4[16], o4[16];
        const float4* qg = (const float4*)(g_q + (bh * NTOK + i) * HD);
#pragma unroll
        for (int t = 0; t < 16; t++) {
            q4[t] = qg[t];
            o4[t] = make_float4(0.f, 0.f, 0.f, 0.f);
        }
        const int qh = i / WIN, qw = i - (i / WIN) * WIN;

        // decomposed rel-pos bias terms (q already scaled)
#pragma unroll 1
        for (int kk = 0; kk < WIN; kk++) {
            const float4* rh4 = (const float4*)(Rh + (qh - kk + WIN - 1) * HD);
            const float4* rw4 = (const float4*)(Rw + (qw - kk + WIN - 1) * HD);
            float sh = 0.f, sw = 0.f;
#pragma unroll
            for (int t = 0; t < 16; t++) {
                float4 a = q4[t], r = rh4[t], w = rw4[t];
                sh += a.x * r.x + a.y * r.y + a.z * r.z + a.w * r.w;
                sw += a.x * w.x + a.y * w.y + a.z * w.z + a.w * w.w;
            }
            BH[i * WIN + kk] = sh;
            BW[i * WIN + kk] = sw;
        }

        float mx = -1e30f, l = 0.f;
#pragma unroll 1
        for (int kh = 0; kh < WIN; kh++) {
            const float bhv = BH[i * WIN + kh];
#pragma unroll 1
            for (int kw = 0; kw < WIN; kw++) {
                const int j = kh * WIN + kw;
                float s = bhv + BW[i * WIN + kw];
                const float4* kr = (const float4*)(Ks + j * HD);
#pragma unroll
                for (int t = 0; t < 16; t++) {
                    float4 a = q4[t], kv = kr[t];
                    s += a.x * kv.x + a.y * kv.y + a.z * kv.z + a.w * kv.w;
                }
                if (s > mx) {              // rare: rescale path
                    const float alpha = __expf(mx - s);
                    l *= alpha;
#pragma unroll
                    for (int t = 0; t < 16; t++) {
                        o4[t].x *= alpha; o4[t].y *= alpha;
                        o4[t].z *= alpha; o4[t].w *= alpha;
                    }
                    mx = s;
                }
                const float p = __expf(s - mx);
                l += p;
                const float4* vr = (const float4*)(Vs + j * HD);
#pragma unroll
                for (int t = 0; t < 16; t++) {
                    float4 vv = vr[t];
                    o4[t].x += p * vv.x; o4[t].y += p * vv.y;
                    o4[t].z += p * vv.z; o4[t].w += p * vv.w;
                }
            }
        }

        const float inv = 1.f / l;
        const int b = bh / NH, h = bh - (bh / NH) * NH;
        float4* og = (float4*)(g_ao + (b * NTOK + i) * DIM + h * HD);
#pragma unroll
        for (int t = 0; t < 16; t++) {
            o4[t].x *= inv; o4[t].y *= inv; o4[t].z *= inv; o4[t].w *= inv;
            og[t] = o4[t];
        }
    }
}

// =========================================================================
extern "C" void kernel_launch(void* const* d_in, const int* in_sizes, int n_in,
                              void* d_out, int out_size)
{
    const float* x      = (const float*)d_in[0];
    const float* qkv_w  = (const float*)d_in[1];
    const float* qkv_b  = (const float*)d_in[2];
    const float* relh   = (const float*)d_in[3];
    const float* relw   = (const float*)d_in[4];
    const float* proj_w = (const float*)d_in[5];
    const float* proj_b = (const float*)d_in[6];
    float* out = (float*)d_out;

    const int smem_bytes = SM_TOT * sizeof(float);  // 136128
    cudaFuncSetAttribute(attn_kernel,
                         cudaFuncAttributeMaxDynamicSharedMemorySize, smem_bytes);

    // 1) QKV GEMM: [50176,768] x [2304,768]^T -> scatter into g_q/g_k/g_v
    gemm_nt<0><<<dim3(2304 / 128, MTOT / 128), 256>>>(x, qkv_w, qkv_b, nullptr);

    // 2) fused attention per (b, head)
    attn_kernel<<<BATCH * NH, 224, smem_bytes>>>(relh, relw);

    // 3) proj GEMM: [50176,768] x [768,768]^T + bias -> d_out
    gemm_nt<1><<<dim3(DIM / 128, MTOT / 128), 256>>>(nullptr, proj_w, proj_b, out);
}

// round 2
// speedup vs baseline: 1.4134x; 1.4134x over previous
#include <cuda_runtime.h>
#include <cstdint>

// ---------------- problem constants ----------------
#define BATCH   256
#define NH      12
#define HD      64
#define DIM     768          // NH*HD
#define WIN     14
#define NTOK    196          // WIN*WIN
#define MTOT    (BATCH*NTOK) // 50176
#define REL     27           // 2*WIN-1

// ---------------- scratch (device globals; no allocation allowed) -------
__device__ float g_q[BATCH*NH*NTOK*HD];   // [b][h][n][d], pre-scaled by 1/8
__device__ float g_k[BATCH*NH*NTOK*HD];
__device__ float g_v[BATCH*NH*NTOK*HD];
__device__ float g_ao[MTOT*DIM];          // attention output [b][n][h*64+d]

// =========================================================================
// tf32 mma.sync GEMM with 3xTF32 split precision.
// C[m][c] = sum_k A[m][k] * B[c][k]  (+bias); A,B K-major, K=768.
// CTA tile 128x128, BK=32, 256 threads = 8 warps in 2(M)x4(N) grid,
// warp tile 64x32, mma m16n8k8 (4 mtiles x 4 ntiles).
// MODE 0: QKV epilogue (scatter into g_q/g_k/g_v, scale q)
// MODE 1: plain epilogue into `out` (proj)
// =========================================================================
#define LDT 36               // padded smem row stride (floats); bank = 4*g + t

__device__ __forceinline__ void mma_tf32(float c[4],
                                         uint32_t a0, uint32_t a1, uint32_t a2, uint32_t a3,
                                         uint32_t b0, uint32_t b1)
{
    asm volatile(
        "mma.sync.aligned.m16n8k8.row.col.f32.tf32.tf32.f32 "
        "{%0,%1,%2,%3}, {%4,%5,%6,%7}, {%8,%9}, {%0,%1,%2,%3};"
        : "+f"(c[0]), "+f"(c[1]), "+f"(c[2]), "+f"(c[3])
        : "r"(a0), "r"(a1), "r"(a2), "r"(a3), "r"(b0), "r"(b1));
}

__device__ __forceinline__ void split_hl(float x, uint32_t& hi, uint32_t& lo)
{
    uint32_t xb = __float_as_uint(x);
    hi = xb & 0xFFFFE000u;                       // truncate to tf32 mantissa
    lo = __float_as_uint(x - __uint_as_float(hi)); // residual (mma truncates it)
}

template<int MODE>
__global__ __launch_bounds__(256) void gemm_mma(const float* __restrict__ A,
                                                const float* __restrict__ Bm,
                                                const float* __restrict__ bias,
                                                float* __restrict__ out)
{
    __shared__ float As[128 * LDT];
    __shared__ float Bs[128 * LDT];

    const int tid = threadIdx.x;
    const int m0  = blockIdx.y * 128;
    const int n0  = blockIdx.x * 128;

    const int w    = tid >> 5;
    const int lane = tid & 31;
    const int g    = lane >> 2;       // group 0..7
    const int t    = lane & 3;        // 0..3
    const int wm   = (w >> 2) * 64;   // warp M offset 0/64
    const int wn   = (w & 3) * 32;    // warp N offset 0..96

    // global loader mapping: 128 rows x 32 k, float4 per thread per row-chunk
    const int lr = tid >> 3;          // 0..31
    const int lc = (tid & 7) * 4;     // 0..28

    const float* Ag = (MODE == 1 ? g_ao : A) + (m0 + lr) * 768 + lc;
    const float* Bg = Bm + (n0 + lr) * 768 + lc;

    float acc[4][4][4];
#pragma unroll
    for (int i = 0; i < 4; i++)
#pragma unroll
        for (int j = 0; j < 4; j++)
#pragma unroll
            for (int r = 0; r < 4; r++) acc[i][j][r] = 0.f;

    float4 pa[4], pb[4];
    // prefetch k0 = 0
#pragma unroll
    for (int i = 0; i < 4; i++) {
        pa[i] = *(const float4*)(Ag + i * 32 * 768);
        pb[i] = *(const float4*)(Bg + i * 32 * 768);
    }

    for (int k0 = 0; k0 < 768; k0 += 32) {
        // store prefetched tile to smem
#pragma unroll
        for (int i = 0; i < 4; i++) {
            *(float4*)&As[(lr + i * 32) * LDT + lc] = pa[i];
            *(float4*)&Bs[(lr + i * 32) * LDT + lc] = pb[i];
        }
        __syncthreads();

        // prefetch next tile
        if (k0 + 32 < 768) {
#pragma unroll
            for (int i = 0; i < 4; i++) {
                pa[i] = *(const float4*)(Ag + k0 + 32 + i * 32 * 768);
                pb[i] = *(const float4*)(Bg + k0 + 32 + i * 32 * 768);
            }
        }

        // compute 4 k-steps of 8
#pragma unroll
        for (int ks = 0; ks < 4; ks++) {
            const int kb = ks * 8;
            uint32_t ah[4][4], al[4][4];   // [mtile][reg]
            uint32_t bh[4][2], bl[4][2];   // [ntile][reg]
#pragma unroll
            for (int mt = 0; mt < 4; mt++) {
                const float* ap = &As[(wm + mt * 16 + g) * LDT + kb + t];
                split_hl(ap[0],           ah[mt][0], al[mt][0]);
                split_hl(ap[8 * LDT],     ah[mt][1], al[mt][1]);
                split_hl(ap[4],           ah[mt][2], al[mt][2]);
                split_hl(ap[8 * LDT + 4], ah[mt][3], al[mt][3]);
            }
#pragma unroll
            for (int nt = 0; nt < 4; nt++) {
                const float* bp = &Bs[(wn + nt * 8 + g) * LDT + kb + t];
                split_hl(bp[0], bh[nt][0], bl[nt][0]);
                split_hl(bp[4], bh[nt][1], bl[nt][1]);
            }
#pragma unroll
            for (int mt = 0; mt < 4; mt++)
#pragma unroll
                for (int nt = 0; nt < 4; nt++) {
                    mma_tf32(acc[mt][nt], al[mt][0], al[mt][1], al[mt][2], al[mt][3],
                             bh[nt][0], bh[nt][1]);
                    mma_tf32(acc[mt][nt], ah[mt][0], ah[mt][1], ah[mt][2], ah[mt][3],
                             bl[nt][0], bl[nt][1]);
                    mma_tf32(acc[mt][nt], ah[mt][0], ah[mt][1], ah[mt][2], ah[mt][3],
                             bh[nt][0], bh[nt][1]);
                }
        }
        __syncthreads();
    }

    // ----- epilogue -----
    // thread owns: rows wm + mt*16 + g (+8), cols wn + nt*8 + 2t (+1)
#pragma unroll
    for (int mt = 0; mt < 4; mt++) {
#pragma unroll
        for (int half = 0; half < 2; half++) {
            const int m = m0 + wm + mt * 16 + g + half * 8;
            if (MODE == 0) {
                const int b = m / NTOK;
                const int n = m - b * NTOK;
#pragma unroll
                for (int nt = 0; nt < 4; nt++) {
#pragma unroll
                    for (int e = 0; e < 2; e++) {
                        const int col = n0 + wn + nt * 8 + 2 * t + e;
                        float v = acc[mt][nt][half * 2 + e] + bias[col];
                        const int which = col / DIM;          // 0=q,1=k,2=v
                        const int rem   = col - which * DIM;
                        const int h     = rem >> 6;
                        const int dd    = rem & 63;
                        const int idx   = ((b * NH + h) * NTOK + n) * HD + dd;
                        if (which == 0)      g_q[idx] = v * 0.125f;
                        else if (which == 1) g_k[idx] = v;
                        else                 g_v[idx] = v;
                    }
                }
            } else {
#pragma unroll
                for (int nt = 0; nt < 4; nt++) {
                    const int col = n0 + wn + nt * 8 + 2 * t;
                    float2 v;
                    v.x = acc[mt][nt][half * 2 + 0] + bias[col];
                    v.y = acc[mt][nt][half * 2 + 1] + bias[col + 1];
                    *(float2*)&out[m * DIM + col] = v;
                }
            }
        }
    }
}

// =========================================================================
// Fused attention: one CTA per (b,h). K/V + rel tables in SMEM. (unchanged)
// =========================================================================
#define SM_KS 0
#define SM_VS (NTOK*HD)                 // 12544
#define SM_RH (2*NTOK*HD)               // 25088
#define SM_RW (SM_RH + REL*HD)          // +1728
#define SM_BH (SM_RW + REL*HD)
#define SM_BW (SM_BH + NTOK*WIN)        // 196*14 = 2744
#define SM_TOT (SM_BW + NTOK*WIN)       // 34032 floats = 136128 B

__global__ __launch_bounds__(224, 1) void attn_kernel(const float* __restrict__ relh,
                                                      const float* __restrict__ relw)
{
    extern __shared__ float sm[];
    float* Ks = sm + SM_KS;
    float* Vs = sm + SM_VS;
    float* Rh = sm + SM_RH;
    float* Rw = sm + SM_RW;
    float* BH = sm + SM_BH;
    float* BW = sm + SM_BW;

    const int bh  = blockIdx.x;          // b*12 + h
    const int tid = threadIdx.x;

    const float4* kbase = (const float4*)(g_k + bh * NTOK * HD);
    const float4* vbase = (const float4*)(g_v + bh * NTOK * HD);
    for (int idx = tid; idx < NTOK * HD / 4; idx += 224) {
        ((float4*)Ks)[idx] = kbase[idx];
        ((float4*)Vs)[idx] = vbase[idx];
    }
    for (int idx = tid; idx < REL * HD / 4; idx += 224) {
        ((float4*)Rh)[idx] = ((const float4*)relh)[idx];
        ((float4*)Rw)[idx] = ((const float4*)relw)[idx];
    }
    __syncthreads();

    const int i = tid;
    if (i < NTOK) {
        float4 q4[16], o4[16];
        const float4* qg = (const float4*)(g_q + (bh * NTOK + i) * HD);
#pragma unroll
        for (int tt = 0; tt < 16; tt++) {
            q4[tt] = qg[tt];
            o4[tt] = make_float4(0.f, 0.f, 0.f, 0.f);
        }
        const int qh = i / WIN, qw = i - (i / WIN) * WIN;

#pragma unroll 1
        for (int kk = 0; kk < WIN; kk++) {
            const float4* rh4 = (const float4*)(Rh + (qh - kk + WIN - 1) * HD);
            const float4* rw4 = (const float4*)(Rw + (qw - kk + WIN - 1) * HD);
            float sh = 0.f, sw = 0.f;
#pragma unroll
            for (int tt = 0; tt < 16; tt++) {
                float4 a = q4[tt], r = rh4[tt], wv = rw4[tt];
                sh += a.x * r.x + a.y * r.y + a.z * r.z + a.w * r.w;
                sw += a.x * wv.x + a.y * wv.y + a.z * wv.z + a.w * wv.w;
            }
            BH[i * WIN + kk] = sh;
            BW[i * WIN + kk] = sw;
        }

        float mx = -1e30f, l = 0.f;
#pragma unroll 1
        for (int kh = 0; kh < WIN; kh++) {
            const float bhv = BH[i * WIN + kh];
#pragma unroll 1
            for (int kw = 0; kw < WIN; kw++) {
                const int j = kh * WIN + kw;
                float s = bhv + BW[i * WIN + kw];
                const float4* kr = (const float4*)(Ks + j * HD);
#pragma unroll
                for (int tt = 0; tt < 16; tt++) {
                    float4 a = q4[tt], kv = kr[tt];
                    s += a.x * kv.x + a.y * kv.y + a.z * kv.z + a.w * kv.w;
                }
                if (s > mx) {
                    const float alpha = __expf(mx - s);
                    l *= alpha;
#pragma unroll
                    for (int tt = 0; tt < 16; tt++) {
                        o4[tt].x *= alpha; o4[tt].y *= alpha;
                        o4[tt].z *= alpha; o4[tt].w *= alpha;
                    }
                    mx = s;
                }
                const float p = __expf(s - mx);
                l += p;
                const float4* vr = (const float4*)(Vs + j * HD);
#pragma unroll
                for (int tt = 0; tt < 16; tt++) {
                    float4 vv = vr[tt];
                    o4[tt].x += p * vv.x; o4[tt].y += p * vv.y;
                    o4[tt].z += p * vv.z; o4[tt].w += p * vv.w;
                }
            }
        }

        const float inv = 1.f / l;
        const int b = bh / NH, h = bh - (bh / NH) * NH;
        float4* og = (float4*)(g_ao + (b * NTOK + i) * DIM + h * HD);
#pragma unroll
        for (int tt = 0; tt < 16; tt++) {
            o4[tt].x *= inv; o4[tt].y *= inv; o4[tt].z *= inv; o4[tt].w *= inv;
            og[tt] = o4[tt];
        }
    }
}

// =========================================================================
extern "C" void kernel_launch(void* const* d_in, const int* in_sizes, int n_in,
                              void* d_out, int out_size)
{
    const float* x      = (const float*)d_in[0];
    const float* qkv_w  = (const float*)d_in[1];
    const float* qkv_b  = (const float*)d_in[2];
    const float* relh   = (const float*)d_in[3];
    const float* relw   = (const float*)d_in[4];
    const float* proj_w = (const float*)d_in[5];
    const float* proj_b = (const float*)d_in[6];
    float* out = (float*)d_out;

    const int smem_bytes = SM_TOT * sizeof(float);  // 136128
    cudaFuncSetAttribute(attn_kernel,
                         cudaFuncAttributeMaxDynamicSharedMemorySize, smem_bytes);

    // 1) QKV GEMM: [50176,768] x [2304,768]^T -> scatter into g_q/g_k/g_v
    gemm_mma<0><<<dim3(2304 / 128, MTOT / 128), 256>>>(x, qkv_w, qkv_b, nullptr);

    // 2) fused attention per (b, head)
    attn_kernel<<<BATCH * NH, 224, smem_bytes>>>(relh, relw);

    // 3) proj GEMM: [50176,768] x [768,768]^T + bias -> d_out
    gemm_mma<1><<<dim3(DIM / 128, MTOT / 128), 256>>>(nullptr, proj_w, proj_b, out);
}

// round 4
// speedup vs baseline: 1.4845x; 1.0503x over previous
#include <cuda_runtime.h>
#include <cstdint>

// ---------------- problem constants ----------------
#define BATCH   256
#define NH      12
#define HD      64
#define DIM     768          // NH*HD
#define WIN     14
#define NTOK    196          // WIN*WIN
#define MTOT    (BATCH*NTOK) // 50176
#define REL     27           // 2*WIN-1

// ---------------- scratch (device globals; no allocation allowed) -------
__device__ float g_q[BATCH*NH*NTOK*HD];   // [b][h][n][d], pre-scaled by 1/8
__device__ float g_k[BATCH*NH*NTOK*HD];
__device__ float g_v[BATCH*NH*NTOK*HD];
__device__ float g_ao[MTOT*DIM];          // attention output [b][n][h*64+d]

// =========================================================================
// bf16 mma.sync GEMM with 3-term bf16 split precision (hi*hi + hi*lo + lo*hi).
// C[m][c] = sum_k A[m][k] * B[c][k]  (+bias); A,B K-major, K=768.
// CTA tile 128x128, BK=32 (2 mma k-steps of 16), 256 threads = 8 warps in
// 2(M)x4(N) grid, warp tile 64x32, mma m16n8k16 (4 mtiles x 4 ntiles).
// MODE 0: QKV epilogue (scatter into g_q/g_k/g_v, scale q)
// MODE 1: plain epilogue into `out` (proj)
// =========================================================================
#define LDT 36               // padded smem row stride (floats)

__device__ __forceinline__ void mma_bf16(float c[4],
                                         uint32_t a0, uint32_t a1, uint32_t a2, uint32_t a3,
                                         uint32_t b0, uint32_t b1)
{
    asm volatile(
        "mma.sync.aligned.m16n8k16.row.col.f32.bf16.bf16.f32 "
        "{%0,%1,%2,%3}, {%4,%5,%6,%7}, {%8,%9}, {%0,%1,%2,%3};"
        : "+f"(c[0]), "+f"(c[1]), "+f"(c[2]), "+f"(c[3])
        : "r"(a0), "r"(a1), "r"(a2), "r"(a3), "r"(b0), "r"(b1));
}

// pack (x0,x1) -> bf16x2 hi (x0 in low half) and bf16x2 residual lo
__device__ __forceinline__ void pack_hl(float x0, float x1, uint32_t& hi, uint32_t& lo)
{
    uint32_t h;
    asm("cvt.rn.bf16x2.f32 %0, %1, %2;" : "=r"(h) : "f"(x1), "f"(x0));
    float h0 = __uint_as_float(h << 16);
    float h1 = __uint_as_float(h & 0xFFFF0000u);
    float l0 = x0 - h0;
    float l1 = x1 - h1;
    uint32_t l;
    asm("cvt.rn.bf16x2.f32 %0, %1, %2;" : "=r"(l) : "f"(l1), "f"(l0));
    hi = h; lo = l;
}

template<int MODE>
__global__ __launch_bounds__(256) void gemm_mma(const float* __restrict__ A,
                                                const float* __restrict__ Bm,
                                                const float* __restrict__ bias,
                                                float* __restrict__ out)
{
    __shared__ float As[128 * LDT];
    __shared__ float Bs[128 * LDT];

    const int tid = threadIdx.x;
    const int m0  = blockIdx.y * 128;
    const int n0  = blockIdx.x * 128;

    const int w    = tid >> 5;
    const int lane = tid & 31;
    const int g    = lane >> 2;       // group 0..7
    const int t    = lane & 3;        // 0..3
    const int wm   = (w >> 2) * 64;   // warp M offset 0/64
    const int wn   = (w & 3) * 32;    // warp N offset 0..96

    // global loader mapping: 128 rows x 32 k, float4 per thread per row-chunk
    const int lr = tid >> 3;          // 0..31
    const int lc = (tid & 7) * 4;     // 0..28

    const float* Ag = (MODE == 1 ? g_ao : A) + (m0 + lr) * 768 + lc;
    const float* Bg = Bm + (n0 + lr) * 768 + lc;

    float acc[4][4][4];
#pragma unroll
    for (int i = 0; i < 4; i++)
#pragma unroll
        for (int j = 0; j < 4; j++)
#pragma unroll
            for (int r = 0; r < 4; r++) acc[i][j][r] = 0.f;

    float4 pa[4], pb[4];
#pragma unroll
    for (int i = 0; i < 4; i++) {
        pa[i] = *(const float4*)(Ag + i * 32 * 768);
        pb[i] = *(const float4*)(Bg + i * 32 * 768);
    }

    for (int k0 = 0; k0 < 768; k0 += 32) {
#pragma unroll
        for (int i = 0; i < 4; i++) {
            *(float4*)&As[(lr + i * 32) * LDT + lc] = pa[i];
            *(float4*)&Bs[(lr + i * 32) * LDT + lc] = pb[i];
        }
        __syncthreads();

        if (k0 + 32 < 768) {
#pragma unroll
            for (int i = 0; i < 4; i++) {
                pa[i] = *(const float4*)(Ag + k0 + 32 + i * 32 * 768);
                pb[i] = *(const float4*)(Bg + k0 + 32 + i * 32 * 768);
            }
        }

        // 2 k-steps of 16
#pragma unroll
        for (int ks = 0; ks < 2; ks++) {
            const int kb = ks * 16;
            uint32_t ah[4][4], al[4][4];   // [mtile][reg]
            uint32_t bh[4][2], bl[4][2];   // [ntile][reg]
#pragma unroll
            for (int mt = 0; mt < 4; mt++) {
                const float* ap = &As[(wm + mt * 16 + g) * LDT + kb + 2 * t];
                float2 v0 = *(const float2*)(ap);
                float2 v1 = *(const float2*)(ap + 8 * LDT);
                float2 v2 = *(const float2*)(ap + 8);
                float2 v3 = *(const float2*)(ap + 8 * LDT + 8);
                pack_hl(v0.x, v0.y, ah[mt][0], al[mt][0]);
                pack_hl(v1.x, v1.y, ah[mt][1], al[mt][1]);
                pack_hl(v2.x, v2.y, ah[mt][2], al[mt][2]);
                pack_hl(v3.x, v3.y, ah[mt][3], al[mt][3]);
            }
#pragma unroll
            for (int nt = 0; nt < 4; nt++) {
                const float* bp = &Bs[(wn + nt * 8 + g) * LDT + kb + 2 * t];
                float2 w0 = *(const float2*)(bp);
                float2 w1 = *(const float2*)(bp + 8);
                pack_hl(w0.x, w0.y, bh[nt][0], bl[nt][0]);
                pack_hl(w1.x, w1.y, bh[nt][1], bl[nt][1]);
            }
#pragma unroll
            for (int mt = 0; mt < 4; mt++)
#pragma unroll
                for (int nt = 0; nt < 4; nt++) {
                    mma_bf16(acc[mt][nt], ah[mt][0], ah[mt][1], ah[mt][2], ah[mt][3],
                             bl[nt][0], bl[nt][1]);
                    mma_bf16(acc[mt][nt], al[mt][0], al[mt][1], al[mt][2], al[mt][3],
                             bh[nt][0], bh[nt][1]);
                    mma_bf16(acc[mt][nt], ah[mt][0], ah[mt][1], ah[mt][2], ah[mt][3],
                             bh[nt][0], bh[nt][1]);
                }
        }
        __syncthreads();
    }

    // ----- epilogue -----
    // thread owns: rows wm + mt*16 + g (+8), cols wn + nt*8 + 2t (+1)
#pragma unroll
    for (int mt = 0; mt < 4; mt++) {
#pragma unroll
        for (int half = 0; half < 2; half++) {
            const int m = m0 + wm + mt * 16 + g + half * 8;
            if (MODE == 0) {
                const int b = m / NTOK;
                const int n = m - b * NTOK;
#pragma unroll
                for (int nt = 0; nt < 4; nt++) {
#pragma unroll
                    for (int e = 0; e < 2; e++) {
                        const int col = n0 + wn + nt * 8 + 2 * t + e;
                        float v = acc[mt][nt][half * 2 + e] + bias[col];
                        const int which = col / DIM;          // 0=q,1=k,2=v
                        const int rem   = col - which * DIM;
                        const int h     = rem >> 6;
                        const int dd    = rem & 63;
                        const int idx   = ((b * NH + h) * NTOK + n) * HD + dd;
                        if (which == 0)      g_q[idx] = v * 0.125f;
                        else if (which == 1) g_k[idx] = v;
                        else                 g_v[idx] = v;
                    }
                }
            } else {
#pragma unroll
                for (int nt = 0; nt < 4; nt++) {
                    const int col = n0 + wn + nt * 8 + 2 * t;
                    float2 v;
                    v.x = acc[mt][nt][half * 2 + 0] + bias[col];
                    v.y = acc[mt][nt][half * 2 + 1] + bias[col + 1];
                    *(float2*)&out[m * DIM + col] = v;
                }
            }
        }
    }
}

// =========================================================================
// Fused attention: one CTA per (b,h), 392 threads = 2 per query.
// Thread tid<196 : query tid,      keys [0,98)
// Thread tid>=196: query tid-196,  keys [98,196)
// Each runs online softmax over its half; halves merged through smem.
// Bias decomposed: half0 computes BH (q . Rh), half1 computes BW (q . Rw).
// =========================================================================
#define OMS 68                          // padded OM row stride (floats)
#define SM_KS 0
#define SM_VS (NTOK*HD)                 // 12544
#define SM_RH (2*NTOK*HD)               // 25088
#define SM_RW (SM_RH + REL*HD)
#define SM_BH (SM_RW + REL*HD)
#define SM_BW (SM_BH + NTOK*WIN)
#define SM_OM (SM_BW + NTOK*WIN)        // partial o, 196 x OMS
#define SM_ML (SM_OM + NTOK*OMS)        // m[196], l[196]
#define SM_TOT (SM_ML + 2*NTOK)         // floats

#define ATHR 392

__global__ __launch_bounds__(ATHR, 1) void attn_kernel(const float* __restrict__ relh,
                                                       const float* __restrict__ relw)
{
    extern __shared__ float sm[];
    float* Ks = sm + SM_KS;
    float* Vs = sm + SM_VS;
    float* Rh = sm + SM_RH;
    float* Rw = sm + SM_RW;
    float* BH = sm + SM_BH;
    float* BW = sm + SM_BW;
    float* OM = sm + SM_OM;
    float* ML = sm + SM_ML;

    const int bh  = blockIdx.x;          // b*12 + h
    const int tid = threadIdx.x;

    const float4* kbase = (const float4*)(g_k + bh * NTOK * HD);
    const float4* vbase = (const float4*)(g_v + bh * NTOK * HD);
    for (int idx = tid; idx < NTOK * HD / 4; idx += ATHR) {
        ((float4*)Ks)[idx] = kbase[idx];
        ((float4*)Vs)[idx] = vbase[idx];
    }
    for (int idx = tid; idx < REL * HD / 4; idx += ATHR) {
        ((float4*)Rh)[idx] = ((const float4*)relh)[idx];
        ((float4*)Rw)[idx] = ((const float4*)relw)[idx];
    }

    const int half = (tid >= NTOK) ? 1 : 0;
    const int qi   = tid - half * NTOK;          // 0..195
    const int qh = qi / WIN, qw = qi - (qi / WIN) * WIN;

    float4 q4[16], o4[16];
    const float4* qg = (const float4*)(g_q + (bh * NTOK + qi) * HD);
#pragma unroll
    for (int tt = 0; tt < 16; tt++) {
        q4[tt] = qg[tt];
        o4[tt] = make_float4(0.f, 0.f, 0.f, 0.f);
    }
    __syncthreads();

    // decomposed rel-pos bias: half0 -> BH row, half1 -> BW row
    {
        const float* Rbase = half ? Rw : Rh;
        const int    qc    = half ? qw : qh;
        float*       Bdst  = (half ? BW : BH) + qi * WIN;
#pragma unroll 1
        for (int kk = 0; kk < WIN; kk++) {
            const float4* r4 = (const float4*)(Rbase + (qc - kk + WIN - 1) * HD);
            float s = 0.f;
#pragma unroll
            for (int tt = 0; tt < 16; tt++) {
                float4 a = q4[tt], r = r4[tt];
                s += a.x * r.x + a.y * r.y + a.z * r.z + a.w * r.w;
            }
            Bdst[kk] = s;
        }
    }
    __syncthreads();

    // online softmax over this thread's 98 keys (7 kh rows x 14 kw)
    float mx = -1e30f, l = 0.f;
    const int kh0 = half * 7;
#pragma unroll 1
    for (int kh = kh0; kh < kh0 + 7; kh++) {
        const float bhv = BH[qi * WIN + kh];
#pragma unroll 1
        for (int kw = 0; kw < WIN; kw++) {
            const int j = kh * WIN + kw;
            float s = bhv + BW[qi * WIN + kw];
            const float4* kr = (const float4*)(Ks + j * HD);
#pragma unroll
            for (int tt = 0; tt < 16; tt++) {
                float4 a = q4[tt], kv = kr[tt];
                s += a.x * kv.x + a.y * kv.y + a.z * kv.z + a.w * kv.w;
            }
            if (s > mx) {
                const float alpha = __expf(mx - s);
                l *= alpha;
#pragma unroll
                for (int tt = 0; tt < 16; tt++) {
                    o4[tt].x *= alpha; o4[tt].y *= alpha;
                    o4[tt].z *= alpha; o4[tt].w *= alpha;
                }
                mx = s;
            }
            const float p = __expf(s - mx);
            l += p;
            const float4* vr = (const float4*)(Vs + j * HD);
#pragma unroll
            for (int tt = 0; tt < 16; tt++) {
                float4 vv = vr[tt];
                o4[tt].x += p * vv.x; o4[tt].y += p * vv.y;
                o4[tt].z += p * vv.z; o4[tt].w += p * vv.w;
            }
        }
    }

    // merge the two halves
    if (half) {
        ML[qi]        = mx;
        ML[NTOK + qi] = l;
        float* om = OM + qi * OMS;
#pragma unroll
        for (int tt = 0; tt < 16; tt++)
            *(float4*)(om + 4 * tt) = o4[tt];
    }
    __syncthreads();
    if (!half) {
        const float m1 = ML[qi], l1 = ML[NTOK + qi];
        const float m  = fmaxf(mx, m1);
        const float f0 = __expf(mx - m);
        const float f1 = __expf(m1 - m);
        const float inv = 1.f / (l * f0 + l1 * f1);
        const float* om = OM + qi * OMS;

        const int b = bh / NH, h = bh - (bh / NH) * NH;
        float4* og = (float4*)(g_ao + (b * NTOK + qi) * DIM + h * HD);
#pragma unroll
        for (int tt = 0; tt < 16; tt++) {
            float4 o1 = *(const float4*)(om + 4 * tt);
            float4 v;
            v.x = (o4[tt].x * f0 + o1.x * f1) * inv;
            v.y = (o4[tt].y * f0 + o1.y * f1) * inv;
            v.z = (o4[tt].z * f0 + o1.z * f1) * inv;
            v.w = (o4[tt].w * f0 + o1.w * f1) * inv;
            og[tt] = v;
        }
    }
}

// =========================================================================
extern "C" void kernel_launch(void* const* d_in, const int* in_sizes, int n_in,
                              void* d_out, int out_size)
{
    const float* x      = (const float*)d_in[0];
    const float* qkv_w  = (const float*)d_in[1];
    const float* qkv_b  = (const float*)d_in[2];
    const float* relh   = (const float*)d_in[3];
    const float* relw   = (const float*)d_in[4];
    const float* proj_w = (const float*)d_in[5];
    const float* proj_b = (const float*)d_in[6];
    float* out = (float*)d_out;

    const int smem_bytes = SM_TOT * (int)sizeof(float);
    cudaFuncSetAttribute(attn_kernel,
                         cudaFuncAttributeMaxDynamicSharedMemorySize, smem_bytes);

    // 1) QKV GEMM: [50176,768] x [2304,768]^T -> scatter into g_q/g_k/g_v
    gemm_mma<0><<<dim3(2304 / 128, MTOT / 128), 256>>>(x, qkv_w, qkv_b, nullptr);

    // 2) fused attention per (b, head)
    attn_kernel<<<BATCH * NH, ATHR, smem_bytes>>>(relh, relw);

    // 3) proj GEMM: [50176,768] x [768,768]^T + bias -> d_out
    gemm_mma<1><<<dim3(DIM / 128, MTOT / 128), 256>>>(nullptr, proj_w, proj_b, out);
}

// round 5
// speedup vs baseline: 1.8842x; 1.2693x over previous
#include <cuda_runtime.h>
#include <cuda_bf16.h>
#include <cstdint>

// ---------------- problem constants ----------------
#define BATCH   256
#define NH      12
#define HD      64
#define DIM     768          // NH*HD
#define WIN     14
#define NTOK    196          // WIN*WIN
#define MTOT    (BATCH*NTOK) // 50176
#define REL     27           // 2*WIN-1

// ---------------- scratch (device globals; no allocation allowed) -------
__device__ float g_q[BATCH*NH*NTOK*HD];   // [b][h][n][d], pre-scaled by 1/8
__device__ float g_k[BATCH*NH*NTOK*HD];   // [b][h][n][d]
__device__ float g_v[BATCH*NH*NTOK*HD];   // TRANSPOSED: [b][h][d][n]
__device__ float g_ao[MTOT*DIM];          // attention output [b][n][h*64+d]

// =========================================================================
// common mma helpers (verified in round 4)
// =========================================================================
__device__ __forceinline__ void mma_bf16(float c[4],
                                         uint32_t a0, uint32_t a1, uint32_t a2, uint32_t a3,
                                         uint32_t b0, uint32_t b1)
{
    asm volatile(
        "mma.sync.aligned.m16n8k16.row.col.f32.bf16.bf16.f32 "
        "{%0,%1,%2,%3}, {%4,%5,%6,%7}, {%8,%9}, {%0,%1,%2,%3};"
        : "+f"(c[0]), "+f"(c[1]), "+f"(c[2]), "+f"(c[3])
        : "r"(a0), "r"(a1), "r"(a2), "r"(a3), "r"(b0), "r"(b1));
}

// pack (x0,x1) -> bf16x2 hi (x0 in low half) and bf16x2 residual lo
__device__ __forceinline__ void pack_hl(float x0, float x1, uint32_t& hi, uint32_t& lo)
{
    uint32_t h;
    asm("cvt.rn.bf16x2.f32 %0, %1, %2;" : "=r"(h) : "f"(x1), "f"(x0));
    float h0 = __uint_as_float(h << 16);
    float h1 = __uint_as_float(h & 0xFFFF0000u);
    float l0 = x0 - h0;
    float l1 = x1 - h1;
    uint32_t l;
    asm("cvt.rn.bf16x2.f32 %0, %1, %2;" : "=r"(l) : "f"(l1), "f"(l0));
    hi = h; lo = l;
}

// =========================================================================
// bf16 mma.sync GEMM with 3-term split (unchanged from round 4 except
// the V-transpose write in the MODE 0 epilogue).
// =========================================================================
#define LDT 36               // padded smem row stride (floats)

template<int MODE>
__global__ __launch_bounds__(256) void gemm_mma(const float* __restrict__ A,
                                                const float* __restrict__ Bm,
                                                const float* __restrict__ bias,
                                                float* __restrict__ out)
{
    __shared__ float As[128 * LDT];
    __shared__ float Bs[128 * LDT];

    const int tid = threadIdx.x;
    const int m0  = blockIdx.y * 128;
    const int n0  = blockIdx.x * 128;

    const int w    = tid >> 5;
    const int lane = tid & 31;
    const int g    = lane >> 2;
    const int t    = lane & 3;
    const int wm   = (w >> 2) * 64;
    const int wn   = (w & 3) * 32;

    const int lr = tid >> 3;
    const int lc = (tid & 7) * 4;

    const float* Ag = (MODE == 1 ? g_ao : A) + (m0 + lr) * 768 + lc;
    const float* Bg = Bm + (n0 + lr) * 768 + lc;

    float acc[4][4][4];
#pragma unroll
    for (int i = 0; i < 4; i++)
#pragma unroll
        for (int j = 0; j < 4; j++)
#pragma unroll
            for (int r = 0; r < 4; r++) acc[i][j][r] = 0.f;

    float4 pa[4], pb[4];
#pragma unroll
    for (int i = 0; i < 4; i++) {
        pa[i] = *(const float4*)(Ag + i * 32 * 768);
        pb[i] = *(const float4*)(Bg + i * 32 * 768);
    }

    for (int k0 = 0; k0 < 768; k0 += 32) {
#pragma unroll
        for (int i = 0; i < 4; i++) {
            *(float4*)&As[(lr + i * 32) * LDT + lc] = pa[i];
            *(float4*)&Bs[(lr + i * 32) * LDT + lc] = pb[i];
        }
        __syncthreads();

        if (k0 + 32 < 768) {
#pragma unroll
            for (int i = 0; i < 4; i++) {
                pa[i] = *(const float4*)(Ag + k0 + 32 + i * 32 * 768);
                pb[i] = *(const float4*)(Bg + k0 + 32 + i * 32 * 768);
            }
        }

#pragma unroll
        for (int ks = 0; ks < 2; ks++) {
            const int kb = ks * 16;
            uint32_t ah[4][4], al[4][4];
            uint32_t bh[4][2], bl[4][2];
#pragma unroll
            for (int mt = 0; mt < 4; mt++) {
                const float* ap = &As[(wm + mt * 16 + g) * LDT + kb + 2 * t];
                float2 v0 = *(const float2*)(ap);
                float2 v1 = *(const float2*)(ap + 8 * LDT);
                float2 v2 = *(const float2*)(ap + 8);
                float2 v3 = *(const float2*)(ap + 8 * LDT + 8);
                pack_hl(v0.x, v0.y, ah[mt][0], al[mt][0]);
                pack_hl(v1.x, v1.y, ah[mt][1], al[mt][1]);
                pack_hl(v2.x, v2.y, ah[mt][2], al[mt][2]);
                pack_hl(v3.x, v3.y, ah[mt][3], al[mt][3]);
            }
#pragma unroll
            for (int nt = 0; nt < 4; nt++) {
                const float* bp = &Bs[(wn + nt * 8 + g) * LDT + kb + 2 * t];
                float2 w0 = *(const float2*)(bp);
                float2 w1 = *(const float2*)(bp + 8);
                pack_hl(w0.x, w0.y, bh[nt][0], bl[nt][0]);
                pack_hl(w1.x, w1.y, bh[nt][1], bl[nt][1]);
            }
#pragma unroll
            for (int mt = 0; mt < 4; mt++)
#pragma unroll
                for (int nt = 0; nt < 4; nt++) {
                    mma_bf16(acc[mt][nt], ah[mt][0], ah[mt][1], ah[mt][2], ah[mt][3],
                             bl[nt][0], bl[nt][1]);
                    mma_bf16(acc[mt][nt], al[mt][0], al[mt][1], al[mt][2], al[mt][3],
                             bh[nt][0], bh[nt][1]);
                    mma_bf16(acc[mt][nt], ah[mt][0], ah[mt][1], ah[mt][2], ah[mt][3],
                             bh[nt][0], bh[nt][1]);
                }
        }
        __syncthreads();
    }

#pragma unroll
    for (int mt = 0; mt < 4; mt++) {
#pragma unroll
        for (int half = 0; half < 2; half++) {
            const int m = m0 + wm + mt * 16 + g + half * 8;
            if (MODE == 0) {
                const int b = m / NTOK;
                const int n = m - b * NTOK;
#pragma unroll
                for (int nt = 0; nt < 4; nt++) {
#pragma unroll
                    for (int e = 0; e < 2; e++) {
                        const int col = n0 + wn + nt * 8 + 2 * t + e;
                        float v = acc[mt][nt][half * 2 + e] + bias[col];
                        const int which = col / DIM;          // 0=q,1=k,2=v
                        const int rem   = col - which * DIM;
                        const int h     = rem >> 6;
                        const int dd    = rem & 63;
                        if (which == 0)
                            g_q[((b * NH + h) * NTOK + n) * HD + dd] = v * 0.125f;
                        else if (which == 1)
                            g_k[((b * NH + h) * NTOK + n) * HD + dd] = v;
                        else // V stored transposed: [b][h][d][n]
                            g_v[((b * NH + h) * HD + dd) * NTOK + n] = v;
                    }
                }
            } else {
#pragma unroll
                for (int nt = 0; nt < 4; nt++) {
                    const int col = n0 + wn + nt * 8 + 2 * t;
                    float2 v;
                    v.x = acc[mt][nt][half * 2 + 0] + bias[col];
                    v.y = acc[mt][nt][half * 2 + 1] + bias[col + 1];
                    *(float2*)&out[m * DIM + col] = v;
                }
            }
        }
    }
}

// =========================================================================
// Tensor-core flash attention, one CTA per (b,h).
// 224 threads = 7 warps; M padded to 208 (13 m16 tiles; warp 6 has 1 tile).
// Keys in 4 chunks of 64 (chunk 3 masked past 195). bf16 3-term split for
// QK^T and P.V. No online max (scores bounded, exp can't overflow).
// =========================================================================
#define QS_STR  68                                // Q smem row stride (floats)
#define KS_STR  72                                // K/Vt smem row stride (bf16)
#define SQ_OFF  0                                 // fp32 [208][QS_STR]
#define SRH_OFF (208*QS_STR*4)                    // 56576
#define SRW_OFF (SRH_OFF + REL*HD*4)              // +6912
#define SBH_OFF (SRW_OFF + REL*HD*4)              // fp32 [208*14]
#define SBW_OFF (SBH_OFF + 208*14*4)
#define SKH_OFF (SBW_OFF + 208*14*4)              // bf16 [64][KS_STR]
#define SKL_OFF (SKH_OFF + 64*KS_STR*2)
#define SVH_OFF (SKL_OFF + 64*KS_STR*2)
#define SVL_OFF (SVH_OFF + 64*KS_STR*2)
#define ATT_SMEM (SVL_OFF + 64*KS_STR*2)          // 130560 bytes

__global__ __launch_bounds__(224, 1) void attn_mma(const float* __restrict__ relh,
                                                   const float* __restrict__ relw)
{
    extern __shared__ char smc[];
    float* QS = (float*)(smc + SQ_OFF);
    float* RH = (float*)(smc + SRH_OFF);
    float* RW = (float*)(smc + SRW_OFF);
    float* BH = (float*)(smc + SBH_OFF);
    float* BW = (float*)(smc + SBW_OFF);
    __nv_bfloat16* KH = (__nv_bfloat16*)(smc + SKH_OFF);
    __nv_bfloat16* KL = (__nv_bfloat16*)(smc + SKL_OFF);
    __nv_bfloat16* VH = (__nv_bfloat16*)(smc + SVH_OFF);
    __nv_bfloat16* VL = (__nv_bfloat16*)(smc + SVL_OFF);

    const int bh  = blockIdx.x;
    const int tid = threadIdx.x;
    const int w    = tid >> 5;
    const int lane = tid & 31;
    const int g    = lane >> 2;
    const int t    = lane & 3;
    const int nmt  = (w == 6) ? 1 : 2;
    const int mrow0 = w * 32;

    const float* qg = g_q + bh * NTOK * HD;
    const float* kg = g_k + bh * NTOK * HD;
    const float* vg = g_v + bh * HD * NTOK;    // transposed [d][n]

    // ---- prologue: stage Q (fp32) + rel tables ----
    for (int idx = tid; idx < 208 * HD; idx += 224) {
        const int r = idx >> 6, c = idx & 63;
        QS[r * QS_STR + c] = (r < NTOK) ? qg[idx] : 0.f;
    }
    for (int idx = tid; idx < REL * HD / 4; idx += 224) {
        ((float4*)RH)[idx] = ((const float4*)relh)[idx];
        ((float4*)RW)[idx] = ((const float4*)relw)[idx];
    }
    __syncthreads();

    // ---- decomposed rel-pos bias (scalar; q from global regs) ----
    if (tid < NTOK) {
        float4 q4[16];
        const float4* qr = (const float4*)(qg + tid * HD);
#pragma unroll
        for (int i = 0; i < 16; i++) q4[i] = qr[i];
        const int qh = tid / WIN, qw = tid - qh * WIN;
#pragma unroll 1
        for (int kk = 0; kk < WIN; kk++) {
            const float4* rh4 = (const float4*)(RH + (qh - kk + WIN - 1) * HD);
            const float4* rw4 = (const float4*)(RW + (qw - kk + WIN - 1) * HD);
            float sh = 0.f, sw = 0.f;
#pragma unroll
            for (int i = 0; i < 16; i++) {
                float4 a = q4[i], r = rh4[i], wv = rw4[i];
                sh += a.x * r.x + a.y * r.y + a.z * r.z + a.w * r.w;
                sw += a.x * wv.x + a.y * wv.y + a.z * wv.z + a.w * wv.w;
            }
            BH[tid * WIN + kk] = sh;
            BW[tid * WIN + kk] = sw;
        }
    } else if (tid < 208) {  // zero pad rows so garbage never enters exp
#pragma unroll
        for (int kk = 0; kk < WIN; kk++) {
            BH[tid * WIN + kk] = 0.f;
            BW[tid * WIN + kk] = 0.f;
        }
    }

    // ---- Q fragments (hoisted; same across chunks) ----
    uint32_t qfh[2][4][4], qfl[2][4][4];
#pragma unroll
    for (int mt = 0; mt < 2; mt++) {
        if (mt < nmt) {
            const int rb = mrow0 + mt * 16 + g;
#pragma unroll
            for (int kt = 0; kt < 4; kt++) {
                const float* ap = &QS[rb * QS_STR + kt * 16 + 2 * t];
                float2 v0 = *(const float2*)(ap);
                float2 v1 = *(const float2*)(ap + 8 * QS_STR);
                float2 v2 = *(const float2*)(ap + 8);
                float2 v3 = *(const float2*)(ap + 8 * QS_STR + 8);
                pack_hl(v0.x, v0.y, qfh[mt][kt][0], qfl[mt][kt][0]);
                pack_hl(v1.x, v1.y, qfh[mt][kt][1], qfl[mt][kt][1]);
                pack_hl(v2.x, v2.y, qfh[mt][kt][2], qfl[mt][kt][2]);
                pack_hl(v3.x, v3.y, qfh[mt][kt][3], qfl[mt][kt][3]);
            }
        }
    }

    float oacc[2][8][4];
#pragma unroll
    for (int i = 0; i < 2; i++)
#pragma unroll
        for (int j = 0; j < 8; j++)
#pragma unroll
            for (int r = 0; r < 4; r++) oacc[i][j][r] = 0.f;
    float lsum[2][2] = {{0.f, 0.f}, {0.f, 0.f}};

    // ---- key chunks ----
#pragma unroll 1
    for (int chunk = 0; chunk < 4; chunk++) {
        const int j0 = chunk * 64;
        __syncthreads();   // previous chunk's mma reads done; bias ready

        // stage K chunk [64 keys][64 d] and Vt chunk [64 d][64 keys], split
        for (int idx = tid; idx < 64 * 64; idx += 224) {
            const int r = idx >> 6, c = idx & 63;
            // K: row=key, col=d
            float kvv = (j0 + r < NTOK) ? kg[(j0 + r) * HD + c] : 0.f;
            __nv_bfloat16 hb = __float2bfloat16(kvv);
            KH[r * KS_STR + c] = hb;
            KL[r * KS_STR + c] = __float2bfloat16(kvv - __bfloat162float(hb));
            // Vt: row=d, col=key
            float vvv = (j0 + c < NTOK) ? vg[r * NTOK + j0 + c] : 0.f;
            __nv_bfloat16 vb = __float2bfloat16(vvv);
            VH[r * KS_STR + c] = vb;
            VL[r * KS_STR + c] = __float2bfloat16(vvv - __bfloat162float(vb));
        }
        __syncthreads();

        // S = Q K^T over this chunk: sacc[mt][nt][4]
        float sacc[2][8][4];
#pragma unroll
        for (int i = 0; i < 2; i++)
#pragma unroll
            for (int j = 0; j < 8; j++)
#pragma unroll
                for (int r = 0; r < 4; r++) sacc[i][j][r] = 0.f;

#pragma unroll
        for (int kt = 0; kt < 4; kt++) {
#pragma unroll
            for (int nt = 0; nt < 8; nt++) {
                const int krow = (nt * 8 + g) * KS_STR + kt * 16 + 2 * t;
                uint32_t kh0 = *(const uint32_t*)&KH[krow];
                uint32_t kh1 = *(const uint32_t*)&KH[krow + 8];
                uint32_t kl0 = *(const uint32_t*)&KL[krow];
                uint32_t kl1 = *(const uint32_t*)&KL[krow + 8];
#pragma unroll
                for (int mt = 0; mt < 2; mt++) {
                    if (mt < nmt) {
                        mma_bf16(sacc[mt][nt], qfh[mt][kt][0], qfh[mt][kt][1],
                                 qfh[mt][kt][2], qfh[mt][kt][3], kl0, kl1);
                        mma_bf16(sacc[mt][nt], qfl[mt][kt][0], qfl[mt][kt][1],
                                 qfl[mt][kt][2], qfl[mt][kt][3], kh0, kh1);
                        mma_bf16(sacc[mt][nt], qfh[mt][kt][0], qfh[mt][kt][1],
                                 qfh[mt][kt][2], qfh[mt][kt][3], kh0, kh1);
                    }
                }
            }
        }

        // bias + exp (+ mask) -> P (stored back in sacc), accumulate l
#pragma unroll
        for (int mt = 0; mt < 2; mt++) {
            if (mt < nmt) {
                const int r0 = mrow0 + mt * 16 + g;
                const int r1 = r0 + 8;
#pragma unroll
                for (int nt = 0; nt < 8; nt++) {
#pragma unroll
                    for (int e = 0; e < 2; e++) {
                        const int c = j0 + nt * 8 + 2 * t + e;
                        float p0 = 0.f, p1 = 0.f;
                        if (c < NTOK) {
                            const int kh = c / WIN;
                            const int kw = c - kh * WIN;
                            p0 = __expf(sacc[mt][nt][e]     + BH[r0 * WIN + kh] + BW[r0 * WIN + kw]);
                            p1 = __expf(sacc[mt][nt][2 + e] + BH[r1 * WIN + kh] + BW[r1 * WIN + kw]);
                        }
                        sacc[mt][nt][e]     = p0;
                        sacc[mt][nt][2 + e] = p1;
                        lsum[mt][0] += p0;
                        lsum[mt][1] += p1;
                    }
                }
            }
        }

        // O += P V : P fragments from sacc (C->A identity), V from smem
#pragma unroll
        for (int mt = 0; mt < 2; mt++) {
            if (mt < nmt) {
#pragma unroll
                for (int kt = 0; kt < 4; kt++) {
                    uint32_t ph[4], pl[4];
                    pack_hl(sacc[mt][2*kt][0],   sacc[mt][2*kt][1],   ph[0], pl[0]);
                    pack_hl(sacc[mt][2*kt][2],   sacc[mt][2*kt][3],   ph[1], pl[1]);
                    pack_hl(sacc[mt][2*kt+1][0], sacc[mt][2*kt+1][1], ph[2], pl[2]);
                    pack_hl(sacc[mt][2*kt+1][2], sacc[mt][2*kt+1][3], ph[3], pl[3]);
#pragma unroll
                    for (int nt = 0; nt < 8; nt++) {
                        const int vrow = (nt * 8 + g) * KS_STR + kt * 16 + 2 * t;
                        uint32_t vh0 = *(const uint32_t*)&VH[vrow];
                        uint32_t vh1 = *(const uint32_t*)&VH[vrow + 8];
                        uint32_t vl0 = *(const uint32_t*)&VL[vrow];
                        uint32_t vl1 = *(const uint32_t*)&VL[vrow + 8];
                        mma_bf16(oacc[mt][nt], ph[0], ph[1], ph[2], ph[3], vl0, vl1);
                        mma_bf16(oacc[mt][nt], pl[0], pl[1], pl[2], pl[3], vh0, vh1);
                        mma_bf16(oacc[mt][nt], ph[0], ph[1], ph[2], ph[3], vh0, vh1);
                    }
                }
            }
        }
    }

    // ---- finalize: reduce l across the t-quad, normalize, store ----
#pragma unroll
    for (int mt = 0; mt < 2; mt++) {
#pragma unroll
        for (int hf = 0; hf < 2; hf++) {
            lsum[mt][hf] += __shfl_xor_sync(0xffffffff, lsum[mt][hf], 1);
            lsum[mt][hf] += __shfl_xor_sync(0xffffffff, lsum[mt][hf], 2);
        }
    }

    const int b = bh / NH, h = bh - (bh / NH) * NH;
#pragma unroll
    for (int mt = 0; mt < 2; mt++) {
        if (mt < nmt) {
            const int r0 = mrow0 + mt * 16 + g;
            const float inv0 = 1.f / lsum[mt][0];
            const float inv1 = 1.f / lsum[mt][1];
            if (r0 < NTOK) {
                float* dst = g_ao + (b * NTOK + r0) * DIM + h * HD;
#pragma unroll
                for (int nt = 0; nt < 8; nt++) {
                    float2 v;
                    v.x = oacc[mt][nt][0] * inv0;
                    v.y = oacc[mt][nt][1] * inv0;
                    *(float2*)&dst[nt * 8 + 2 * t] = v;
                }
            }
            if (r0 + 8 < NTOK) {
                float* dst = g_ao + (b * NTOK + r0 + 8) * DIM + h * HD;
#pragma unroll
                for (int nt = 0; nt < 8; nt++) {
                    float2 v;
                    v.x = oacc[mt][nt][2] * inv1;
                    v.y = oacc[mt][nt][3] * inv1;
                    *(float2*)&dst[nt * 8 + 2 * t] = v;
                }
            }
        }
    }
}

// =========================================================================
extern "C" void kernel_launch(void* const* d_in, const int* in_sizes, int n_in,
                              void* d_out, int out_size)
{
    const float* x      = (const float*)d_in[0];
    const float* qkv_w  = (const float*)d_in[1];
    const float* qkv_b  = (const float*)d_in[2];
    const float* relh   = (const float*)d_in[3];
    const float* relw   = (const float*)d_in[4];
    const float* proj_w = (const float*)d_in[5];
    const float* proj_b = (const float*)d_in[6];
    float* out = (float*)d_out;

    cudaFuncSetAttribute(attn_mma,
                         cudaFuncAttributeMaxDynamicSharedMemorySize, ATT_SMEM);

    // 1) QKV GEMM: [50176,768] x [2304,768]^T -> g_q/g_k scatter, g_v transposed
    gemm_mma<0><<<dim3(2304 / 128, MTOT / 128), 256>>>(x, qkv_w, qkv_b, nullptr);

    // 2) tensor-core flash attention per (b, head)
    attn_mma<<<BATCH * NH, 224, ATT_SMEM>>>(relh, relw);

    // 3) proj GEMM: [50176,768] x [768,768]^T + bias -> d_out
    gemm_mma<1><<<dim3(DIM / 128, MTOT / 128), 256>>>(nullptr, proj_w, proj_b, out);
}

// round 6
// speedup vs baseline: 1.9340x; 1.0264x over previous
#include <cuda_runtime.h>
#include <cuda_bf16.h>
#include <cstdint>

// ---------------- problem constants ----------------
#define BATCH   256
#define NH      12
#define HD      64
#define DIM     768          // NH*HD
#define WIN     14
#define NTOK    196          // WIN*WIN
#define MTOT    (BATCH*NTOK) // 50176
#define REL     27           // 2*WIN-1

// ---------------- scratch (device globals; no allocation allowed) -------
__device__ float g_q[BATCH*NH*NTOK*HD];   // [b][h][n][d], pre-scaled by 1/8
__device__ float g_k[BATCH*NH*NTOK*HD];   // [b][h][n][d]
__device__ float g_v[BATCH*NH*NTOK*HD];   // TRANSPOSED: [b][h][d][n]
__device__ float g_ao[MTOT*DIM];          // attention output [b][n][h*64+d]

// =========================================================================
// common mma helpers
// =========================================================================
__device__ __forceinline__ void mma_bf16(float c[4],
                                         uint32_t a0, uint32_t a1, uint32_t a2, uint32_t a3,
                                         uint32_t b0, uint32_t b1)
{
    asm volatile(
        "mma.sync.aligned.m16n8k16.row.col.f32.bf16.bf16.f32 "
        "{%0,%1,%2,%3}, {%4,%5,%6,%7}, {%8,%9}, {%0,%1,%2,%3};"
        : "+f"(c[0]), "+f"(c[1]), "+f"(c[2]), "+f"(c[3])
        : "r"(a0), "r"(a1), "r"(a2), "r"(a3), "r"(b0), "r"(b1));
}

// pack (x0,x1) -> bf16x2 hi (x0 in low half) and bf16x2 residual lo
__device__ __forceinline__ void pack_hl(float x0, float x1, uint32_t& hi, uint32_t& lo)
{
    uint32_t h;
    asm("cvt.rn.bf16x2.f32 %0, %1, %2;" : "=r"(h) : "f"(x1), "f"(x0));
    float h0 = __uint_as_float(h << 16);
    float h1 = __uint_as_float(h & 0xFFFF0000u);
    float l0 = x0 - h0;
    float l1 = x1 - h1;
    uint32_t l;
    asm("cvt.rn.bf16x2.f32 %0, %1, %2;" : "=r"(l) : "f"(l1), "f"(l0));
    hi = h; lo = l;
}

// =========================================================================
// bf16 mma.sync GEMM, 3-term split performed ONCE at smem-store time.
// C[m][c] = sum_k A[m][k] * B[c][k]  (+bias); A,B K-major, K=768.
// CTA tile 128x128, BK=32, 256 threads = 8 warps (2M x 4N), warp tile 64x32.
// Smem: bf16 hi/lo tiles, row stride 40 bf16 (80B) -> conflict-free frags.
// MODE 0: QKV epilogue (scatter q/k, v transposed)   MODE 1: proj
// =========================================================================
#define KSTR 40              // bf16 smem row stride

template<int MODE>
__global__ __launch_bounds__(256) void gemm_mma(const float* __restrict__ A,
                                                const float* __restrict__ Bm,
                                                const float* __restrict__ bias,
                                                float* __restrict__ out)
{
    __shared__ __nv_bfloat16 AsH[128 * KSTR];
    __shared__ __nv_bfloat16 AsL[128 * KSTR];
    __shared__ __nv_bfloat16 BsH[128 * KSTR];
    __shared__ __nv_bfloat16 BsL[128 * KSTR];

    const int tid = threadIdx.x;
    const int m0  = blockIdx.y * 128;
    const int n0  = blockIdx.x * 128;

    const int w    = tid >> 5;
    const int lane = tid & 31;
    const int g    = lane >> 2;
    const int t    = lane & 3;
    const int wm   = (w >> 2) * 64;
    const int wn   = (w & 3) * 32;

    // loader: thread -> row lr (0..127), k-offset lc (0 or 16), 16 floats each
    const int lr = tid >> 1;
    const int lc = (tid & 1) * 16;

    const float* Ag = (MODE == 1 ? g_ao : A) + (m0 + lr) * 768 + lc;
    const float* Bg = Bm + (n0 + lr) * 768 + lc;

    float acc[4][4][4];
#pragma unroll
    for (int i = 0; i < 4; i++)
#pragma unroll
        for (int j = 0; j < 4; j++)
#pragma unroll
            for (int r = 0; r < 4; r++) acc[i][j][r] = 0.f;

    float4 pa[4], pb[4];
#pragma unroll
    for (int j = 0; j < 4; j++) {
        pa[j] = *(const float4*)(Ag + 4 * j);
        pb[j] = *(const float4*)(Bg + 4 * j);
    }

    for (int k0 = 0; k0 < 768; k0 += 32) {
        // convert + store (split once per element)
#pragma unroll
        for (int j = 0; j < 4; j++) {
            uint32_t h0, l0, h1, l1;
            pack_hl(pa[j].x, pa[j].y, h0, l0);
            pack_hl(pa[j].z, pa[j].w, h1, l1);
            *(uint32_t*)&AsH[lr * KSTR + lc + 4 * j]     = h0;
            *(uint32_t*)&AsH[lr * KSTR + lc + 4 * j + 2] = h1;
            *(uint32_t*)&AsL[lr * KSTR + lc + 4 * j]     = l0;
            *(uint32_t*)&AsL[lr * KSTR + lc + 4 * j + 2] = l1;
            pack_hl(pb[j].x, pb[j].y, h0, l0);
            pack_hl(pb[j].z, pb[j].w, h1, l1);
            *(uint32_t*)&BsH[lr * KSTR + lc + 4 * j]     = h0;
            *(uint32_t*)&BsH[lr * KSTR + lc + 4 * j + 2] = h1;
            *(uint32_t*)&BsL[lr * KSTR + lc + 4 * j]     = l0;
            *(uint32_t*)&BsL[lr * KSTR + lc + 4 * j + 2] = l1;
        }
        __syncthreads();

        if (k0 + 32 < 768) {
#pragma unroll
            for (int j = 0; j < 4; j++) {
                pa[j] = *(const float4*)(Ag + k0 + 32 + 4 * j);
                pb[j] = *(const float4*)(Bg + k0 + 32 + 4 * j);
            }
        }

#pragma unroll
        for (int ks = 0; ks < 2; ks++) {
            const int kb = ks * 16 + 2 * t;
            uint32_t ah[4][4], al[4][4], bh[4][2], bl[4][2];
#pragma unroll
            for (int mt = 0; mt < 4; mt++) {
                const int ro = (wm + mt * 16 + g) * KSTR + kb;
                ah[mt][0] = *(const uint32_t*)&AsH[ro];
                ah[mt][1] = *(const uint32_t*)&AsH[ro + 8 * KSTR];
                ah[mt][2] = *(const uint32_t*)&AsH[ro + 8];
                ah[mt][3] = *(const uint32_t*)&AsH[ro + 8 * KSTR + 8];
                al[mt][0] = *(const uint32_t*)&AsL[ro];
                al[mt][1] = *(const uint32_t*)&AsL[ro + 8 * KSTR];
                al[mt][2] = *(const uint32_t*)&AsL[ro + 8];
                al[mt][3] = *(const uint32_t*)&AsL[ro + 8 * KSTR + 8];
            }
#pragma unroll
            for (int nt = 0; nt < 4; nt++) {
                const int ro = (wn + nt * 8 + g) * KSTR + kb;
                bh[nt][0] = *(const uint32_t*)&BsH[ro];
                bh[nt][1] = *(const uint32_t*)&BsH[ro + 8];
                bl[nt][0] = *(const uint32_t*)&BsL[ro];
                bl[nt][1] = *(const uint32_t*)&BsL[ro + 8];
            }
#pragma unroll
            for (int mt = 0; mt < 4; mt++)
#pragma unroll
                for (int nt = 0; nt < 4; nt++) {
                    mma_bf16(acc[mt][nt], ah[mt][0], ah[mt][1], ah[mt][2], ah[mt][3],
                             bl[nt][0], bl[nt][1]);
                    mma_bf16(acc[mt][nt], al[mt][0], al[mt][1], al[mt][2], al[mt][3],
                             bh[nt][0], bh[nt][1]);
                    mma_bf16(acc[mt][nt], ah[mt][0], ah[mt][1], ah[mt][2], ah[mt][3],
                             bh[nt][0], bh[nt][1]);
                }
        }
        __syncthreads();
    }

    // ----- epilogue -----
#pragma unroll
    for (int mt = 0; mt < 4; mt++) {
#pragma unroll
        for (int half = 0; half < 2; half++) {
            const int m = m0 + wm + mt * 16 + g + half * 8;
            if (MODE == 0) {
                const int b = m / NTOK;
                const int n = m - b * NTOK;
#pragma unroll
                for (int nt = 0; nt < 4; nt++) {
#pragma unroll
                    for (int e = 0; e < 2; e++) {
                        const int col = n0 + wn + nt * 8 + 2 * t + e;
                        float v = acc[mt][nt][half * 2 + e] + bias[col];
                        const int which = col / DIM;          // 0=q,1=k,2=v
                        const int rem   = col - which * DIM;
                        const int h     = rem >> 6;
                        const int dd    = rem & 63;
                        if (which == 0)
                            g_q[((b * NH + h) * NTOK + n) * HD + dd] = v * 0.125f;
                        else if (which == 1)
                            g_k[((b * NH + h) * NTOK + n) * HD + dd] = v;
                        else // V transposed: [b][h][d][n]
                            g_v[((b * NH + h) * HD + dd) * NTOK + n] = v;
                    }
                }
            } else {
#pragma unroll
                for (int nt = 0; nt < 4; nt++) {
                    const int col = n0 + wn + nt * 8 + 2 * t;
                    float2 v;
                    v.x = acc[mt][nt][half * 2 + 0] + bias[col];
                    v.y = acc[mt][nt][half * 2 + 1] + bias[col + 1];
                    *(float2*)&out[m * DIM + col] = v;
                }
            }
        }
    }
}

// =========================================================================
// Tensor-core flash attention, one CTA per (b,h).
// 416 threads = 13 warps; each warp owns ONE m16 tile (13*16 = 208 >= 196).
// Keys in 4 chunks of 64. bf16 3-term split for QK^T and P.V.
// No online max (scores bounded). Q fragments built straight from global.
// =========================================================================
#define KS_STR  72                                // K/Vt smem row stride (bf16)
#define SRH_OFF 0
#define SRW_OFF (SRH_OFF + REL*HD*4)              // +6912
#define SBH_OFF (SRW_OFF + REL*HD*4)              // fp32 [208*14]
#define SBW_OFF (SBH_OFF + 208*14*4)
#define SKH_OFF (SBW_OFF + 208*14*4)              // bf16 [64][KS_STR]
#define SKL_OFF (SKH_OFF + 64*KS_STR*2)
#define SVH_OFF (SKL_OFF + 64*KS_STR*2)
#define SVL_OFF (SVH_OFF + 64*KS_STR*2)
#define ATT_SMEM (SVL_OFF + 64*KS_STR*2)          // 73984 bytes

#define ATHR 416

__global__ __launch_bounds__(ATHR, 1) void attn_mma(const float* __restrict__ relh,
                                                    const float* __restrict__ relw)
{
    extern __shared__ char smc[];
    float* RH = (float*)(smc + SRH_OFF);
    float* RW = (float*)(smc + SRW_OFF);
    float* BH = (float*)(smc + SBH_OFF);
    float* BW = (float*)(smc + SBW_OFF);
    __nv_bfloat16* KH = (__nv_bfloat16*)(smc + SKH_OFF);
    __nv_bfloat16* KL = (__nv_bfloat16*)(smc + SKL_OFF);
    __nv_bfloat16* VH = (__nv_bfloat16*)(smc + SVH_OFF);
    __nv_bfloat16* VL = (__nv_bfloat16*)(smc + SVL_OFF);

    const int bh  = blockIdx.x;
    const int tid = threadIdx.x;
    const int w    = tid >> 5;
    const int lane = tid & 31;
    const int g    = lane >> 2;
    const int t    = lane & 3;

    const float* qg = g_q + bh * NTOK * HD;
    const float* kg = g_k + bh * NTOK * HD;
    const float* vg = g_v + bh * HD * NTOK;    // transposed [d][n]

    // ---- stage rel tables ----
    for (int idx = tid; idx < REL * HD / 4; idx += ATHR) {
        ((float4*)RH)[idx] = ((const float4*)relh)[idx];
        ((float4*)RW)[idx] = ((const float4*)relw)[idx];
    }
    __syncthreads();

    // ---- decomposed rel-pos bias (scalar, once) ----
    if (tid < NTOK) {
        float4 q4[16];
        const float4* qr = (const float4*)(qg + tid * HD);
#pragma unroll
        for (int i = 0; i < 16; i++) q4[i] = qr[i];
        const int qh = tid / WIN, qw = tid - qh * WIN;
#pragma unroll 1
        for (int kk = 0; kk < WIN; kk++) {
            const float4* rh4 = (const float4*)(RH + (qh - kk + WIN - 1) * HD);
            const float4* rw4 = (const float4*)(RW + (qw - kk + WIN - 1) * HD);
            float sh = 0.f, sw = 0.f;
#pragma unroll
            for (int i = 0; i < 16; i++) {
                float4 a = q4[i], r = rh4[i], wv = rw4[i];
                sh += a.x * r.x + a.y * r.y + a.z * r.z + a.w * r.w;
                sw += a.x * wv.x + a.y * wv.y + a.z * wv.z + a.w * wv.w;
            }
            BH[tid * WIN + kk] = sh;
            BW[tid * WIN + kk] = sw;
        }
    } else if (tid < 208) {
#pragma unroll
        for (int kk = 0; kk < WIN; kk++) {
            BH[tid * WIN + kk] = 0.f;
            BW[tid * WIN + kk] = 0.f;
        }
    }

    // ---- Q fragments from global (once; pad rows clamped -> unused) ----
    const int r0 = w * 16 + g;            // this thread's first C row
    const int r1 = r0 + 8;
    const int rq0 = (r0 < NTOK) ? r0 : NTOK - 1;
    const int rq1 = (r1 < NTOK) ? r1 : NTOK - 1;
    uint32_t qfh[4][4], qfl[4][4];
#pragma unroll
    for (int kt = 0; kt < 4; kt++) {
        const int kc = kt * 16 + 2 * t;
        float2 v0 = *(const float2*)(qg + rq0 * HD + kc);
        float2 v1 = *(const float2*)(qg + rq1 * HD + kc);
        float2 v2 = *(const float2*)(qg + rq0 * HD + kc + 8);
        float2 v3 = *(const float2*)(qg + rq1 * HD + kc + 8);
        pack_hl(v0.x, v0.y, qfh[kt][0], qfl[kt][0]);
        pack_hl(v1.x, v1.y, qfh[kt][1], qfl[kt][1]);
        pack_hl(v2.x, v2.y, qfh[kt][2], qfl[kt][2]);
        pack_hl(v3.x, v3.y, qfh[kt][3], qfl[kt][3]);
    }

    float oacc[8][4];
#pragma unroll
    for (int j = 0; j < 8; j++)
#pragma unroll
        for (int r = 0; r < 4; r++) oacc[j][r] = 0.f;
    float lsum0 = 0.f, lsum1 = 0.f;

    // ---- key chunks ----
#pragma unroll 1
    for (int chunk = 0; chunk < 4; chunk++) {
        const int j0 = chunk * 64;
        __syncthreads();

        // stage K chunk [64 keys][64 d] and Vt chunk [64 d][64 keys], split
        for (int idx = tid; idx < 64 * 64; idx += ATHR) {
            const int r = idx >> 6, c = idx & 63;
            float kvv = (j0 + r < NTOK) ? kg[(j0 + r) * HD + c] : 0.f;
            __nv_bfloat16 hb = __float2bfloat16(kvv);
            KH[r * KS_STR + c] = hb;
            KL[r * KS_STR + c] = __float2bfloat16(kvv - __bfloat162float(hb));
            float vvv = (j0 + c < NTOK) ? vg[r * NTOK + j0 + c] : 0.f;
            __nv_bfloat16 vb = __float2bfloat16(vvv);
            VH[r * KS_STR + c] = vb;
            VL[r * KS_STR + c] = __float2bfloat16(vvv - __bfloat162float(vb));
        }
        __syncthreads();

        // S = Q K^T over this chunk
        float sacc[8][4];
#pragma unroll
        for (int j = 0; j < 8; j++)
#pragma unroll
            for (int r = 0; r < 4; r++) sacc[j][r] = 0.f;

#pragma unroll
        for (int kt = 0; kt < 4; kt++) {
            const int kc = kt * 16 + 2 * t;
#pragma unroll
            for (int nt = 0; nt < 8; nt++) {
                const int krow = (nt * 8 + g) * KS_STR + kc;
                uint32_t kh0 = *(const uint32_t*)&KH[krow];
                uint32_t kh1 = *(const uint32_t*)&KH[krow + 8];
                uint32_t kl0 = *(const uint32_t*)&KL[krow];
                uint32_t kl1 = *(const uint32_t*)&KL[krow + 8];
                mma_bf16(sacc[nt], qfh[kt][0], qfh[kt][1], qfh[kt][2], qfh[kt][3], kl0, kl1);
                mma_bf16(sacc[nt], qfl[kt][0], qfl[kt][1], qfl[kt][2], qfl[kt][3], kh0, kh1);
                mma_bf16(sacc[nt], qfh[kt][0], qfh[kt][1], qfh[kt][2], qfh[kt][3], kh0, kh1);
            }
        }

        // bias + exp (+ column mask) -> P, accumulate l
#pragma unroll
        for (int nt = 0; nt < 8; nt++) {
#pragma unroll
            for (int e = 0; e < 2; e++) {
                const int c = j0 + nt * 8 + 2 * t + e;
                float p0 = 0.f, p1 = 0.f;
                if (c < NTOK) {
                    const int kh = c / WIN;
                    const int kw = c - kh * WIN;
                    p0 = __expf(sacc[nt][e]     + BH[r0 * WIN + kh] + BW[r0 * WIN + kw]);
                    p1 = __expf(sacc[nt][2 + e] + BH[r1 * WIN + kh] + BW[r1 * WIN + kw]);
                }
                sacc[nt][e]     = p0;
                sacc[nt][2 + e] = p1;
                lsum0 += p0;
                lsum1 += p1;
            }
        }

        // O += P V : P fragments from sacc (C->A identity), V from smem
#pragma unroll
        for (int kt = 0; kt < 4; kt++) {
            uint32_t ph[4], pl[4];
            pack_hl(sacc[2*kt][0],   sacc[2*kt][1],   ph[0], pl[0]);
            pack_hl(sacc[2*kt][2],   sacc[2*kt][3],   ph[1], pl[1]);
            pack_hl(sacc[2*kt+1][0], sacc[2*kt+1][1], ph[2], pl[2]);
            pack_hl(sacc[2*kt+1][2], sacc[2*kt+1][3], ph[3], pl[3]);
            const int kc = kt * 16 + 2 * t;
#pragma unroll
            for (int nt = 0; nt < 8; nt++) {
                const int vrow = (nt * 8 + g) * KS_STR + kc;
                uint32_t vh0 = *(const uint32_t*)&VH[vrow];
                uint32_t vh1 = *(const uint32_t*)&VH[vrow + 8];
                uint32_t vl0 = *(const uint32_t*)&VL[vrow];
                uint32_t vl1 = *(const uint32_t*)&VL[vrow + 8];
                mma_bf16(oacc[nt], ph[0], ph[1], ph[2], ph[3], vl0, vl1);
                mma_bf16(oacc[nt], pl[0], pl[1], pl[2], pl[3], vh0, vh1);
                mma_bf16(oacc[nt], ph[0], ph[1], ph[2], ph[3], vh0, vh1);
            }
        }
    }

    // ---- finalize: reduce l across the t-quad, normalize, store ----
    lsum0 += __shfl_xor_sync(0xffffffff, lsum0, 1);
    lsum0 += __shfl_xor_sync(0xffffffff, lsum0, 2);
    lsum1 += __shfl_xor_sync(0xffffffff, lsum1, 1);
    lsum1 += __shfl_xor_sync(0xffffffff, lsum1, 2);

    const int b = bh / NH, h = bh - (bh / NH) * NH;
    const float inv0 = 1.f / lsum0;
    const float inv1 = 1.f / lsum1;
    if (r0 < NTOK) {
        float* dst = g_ao + (b * NTOK + r0) * DIM + h * HD;
#pragma unroll
        for (int nt = 0; nt < 8; nt++) {
            float2 v;
            v.x = oacc[nt][0] * inv0;
            v.y = oacc[nt][1] * inv0;
            *(float2*)&dst[nt * 8 + 2 * t] = v;
        }
    }
    if (r1 < NTOK) {
        float* dst = g_ao + (b * NTOK + r1) * DIM + h * HD;
#pragma unroll
        for (int nt = 0; nt < 8; nt++) {
            float2 v;
            v.x = oacc[nt][2] * inv1;
            v.y = oacc[nt][3] * inv1;
            *(float2*)&dst[nt * 8 + 2 * t] = v;
        }
    }
}

// =========================================================================
extern "C" void kernel_launch(void* const* d_in, const int* in_sizes, int n_in,
                              void* d_out, int out_size)
{
    const float* x      = (const float*)d_in[0];
    const float* qkv_w  = (const float*)d_in[1];
    const float* qkv_b  = (const float*)d_in[2];
    const float* relh   = (const float*)d_in[3];
    const float* relw   = (const float*)d_in[4];
    const float* proj_w = (const float*)d_in[5];
    const float* proj_b = (const float*)d_in[6];
    float* out = (float*)d_out;

    cudaFuncSetAttribute(attn_mma,
                         cudaFuncAttributeMaxDynamicSharedMemorySize, ATT_SMEM);

    // 1) QKV GEMM: [50176,768] x [2304,768]^T -> g_q/g_k scatter, g_v transposed
    gemm_mma<0><<<dim3(2304 / 128, MTOT / 128), 256>>>(x, qkv_w, qkv_b, nullptr);

    // 2) tensor-core flash attention per (b, head)
    attn_mma<<<BATCH * NH, ATHR, ATT_SMEM>>>(relh, relw);

    // 3) proj GEMM: [50176,768] x [768,768]^T + bias -> d_out
    gemm_mma<1><<<dim3(DIM / 128, MTOT / 128), 256>>>(nullptr, proj_w, proj_b, out);
}